// round 15
// baseline (speedup 1.0000x reference)
#include <cuda_runtime.h>
#include <cuda_fp16.h>
#include <cstdint>
#include <math.h>

#define HF 320
#define WF 320

// ---------------- global scratch ----------------
__device__ __align__(16) __half g_feat[(size_t)HF * WF * 128];   // [y][x][ic] fp16, 26 MB
__device__ __align__(16) __half g_w1[18 * 256 * 64];             // swizzled A tiles fp16
__device__ __align__(16) float g_Tp[2][(size_t)HF * WF * 9];     // partial T (oc halves)
__device__ __align__(16) float g_Tbp[2][(size_t)256 * 124 * 9];  // partial border ring
__device__ float g_partial[256];

// ---------------- helpers ----------------
__device__ __forceinline__ uint32_t smem_u32(const void* p) {
    uint32_t a;
    asm("{ .reg .u64 t; cvta.to.shared.u64 t, %1; cvt.u32.u64 %0, t; }" : "=r"(a) : "l"(p));
    return a;
}
__device__ __forceinline__ uint32_t swz(uint32_t o) { return o ^ ((o >> 3) & 0x70); }

__device__ __forceinline__ void cp16(uint32_t dst, const void* src, bool valid) {
    unsigned long long gsrc;
    asm("cvta.to.global.u64 %0, %1;" : "=l"(gsrc) : "l"(src));
    int sz = valid ? 16 : 0;
    asm volatile("cp.async.ca.shared.global [%0], [%1], 16, %2;" :: "r"(dst), "l"(gsrc), "r"(sz));
}
#define CP_COMMIT() asm volatile("cp.async.commit_group;")
#define CP_WAIT0()  asm volatile("cp.async.wait_group 0;")

__device__ __forceinline__ void ldsm_x4(uint32_t& r0, uint32_t& r1, uint32_t& r2, uint32_t& r3,
                                        uint32_t addr) {
    asm volatile("ldmatrix.sync.aligned.m8n8.x4.shared.b16 {%0,%1,%2,%3}, [%4];"
                 : "=r"(r0), "=r"(r1), "=r"(r2), "=r"(r3) : "r"(addr));
}

// ring index <-> local (y,x) on the crop border (124 px)
__device__ __forceinline__ void ring2yx(int idx, int& y, int& x) {
    if (idx < 32)      { y = 0;              x = idx; }
    else if (idx < 64) { y = 31;             x = idx - 32; }
    else if (idx < 94) { y = 1 + (idx - 64); x = 0; }
    else               { y = 1 + (idx - 94); x = 31; }
}
// width-2 frame of the 32x32 crop: 240 rows
__device__ __forceinline__ int frame2row(int y, int x) {
    if (y < 2)   return y * 32 + x;
    if (y >= 30) return 64 + (y - 30) * 32 + x;
    return 128 + (y - 2) * 4 + ((x < 2) ? x : x - 28);
}

// ---------------- P0: feature fp32 [ic][y][x] -> fp16 [y][x][ic] ----------------
__global__ __launch_bounds__(256) void k_prep_feat(const float* __restrict__ f) {
    __shared__ float s[32][33];
    int t = threadIdx.x;
    int bx = blockIdx.x;           // y*10 + xt
    int y = bx / 10, xt = bx % 10;
    int ict = blockIdx.y;          // 4 chunks of 32 ic
    int lx = t & 31, lr = t >> 5;
#pragma unroll
    for (int i = 0; i < 4; i++) {
        int ic = i * 8 + lr;
        s[ic][lx] = f[(size_t)(ict * 32 + ic) * (HF * WF) + (size_t)y * WF + xt * 32 + lx];
    }
    __syncthreads();
#pragma unroll
    for (int i = 0; i < 4; i++) {
        int x = i * 8 + lr;
        g_feat[((size_t)y * WF + xt * 32 + x) * 128 + ict * 32 + lx] = __float2half(s[lx][x]);
    }
}

// ---------------- P1: W1 fp32 [256][128][3][3] -> swizzled fp16 A tiles ----------------
__global__ __launch_bounds__(256) void k_prep_w1(const float* __restrict__ W1) {
    int e = blockIdx.x * 256 + threadIdx.x;   // < 294912
    int i = e & 63;            // ic within chunk
    int r = (e >> 6) & 255;    // oc
    int bi = e >> 14;          // 0..17
    int tap = bi >> 1, c = bi & 1;
    float v = W1[((size_t)r * 128 + c * 64 + i) * 9 + tap];
    *(__half*)((char*)g_w1 + (size_t)bi * 32768 + swz((uint32_t)(r * 128 + i * 2))) =
        __float2half(v);
}

// ---------------- tiny 3rd launch (keeps k_conv as the profiled 4th launch) -------------
__global__ void k_zero() { g_partial[threadIdx.x] = 0.0f; }

// ---------------- conv: map tiles (bx<1080) + border tiles (bx>=1080) -------------------
// 256 thr = 8 warps (2wm x 4wn), warp tile 64oc x 48px, occ 2/SM.
// CTA: M=128 oc (half h), N=192 px (6 map rows, y-padded at 324), K=1152.
// SMEM 102656B: A ring buf0/1 [0,32K), slab plane0 [32768,+34944), plane1 [+34944).
#define PLANE_BYTES 34944     // 273 rows x 128B
#define SLAB_OFF    32768
__global__ __launch_bounds__(256, 2) void k_conv(const int* __restrict__ anchors,
                                                 const float* __restrict__ b1,
                                                 const float* __restrict__ W2) {
    extern __shared__ char smem[];
    const int tid = threadIdx.x, lane = tid & 31, wid = tid >> 5;
    const int g = lane >> 2, tig = lane & 3;
    const int wm = wid >> 2, wn = wid & 3;         // wm 0..1, wn 0..3
    const int bx = blockIdx.x;
    const bool border = (bx >= 1080);
    int ty = 0, tx = 0, a = 0, x0 = 0, y0 = 0, h;
    if (!border) { int tile = bx >> 1; h = bx & 1; ty = tile / 10; tx = tile % 10; }
    else { int b = bx - 1080; a = b >> 1; h = b & 1;
           x0 = anchors[a * 4 + 0]; y0 = anchors[a * 4 + 2]; }
    const uint32_t sb = smem_u32(smem);

    const int a_row = (lane & 7) + ((lane >> 3) & 1) * 8;
    const int a_kb  = (lane >> 4) * 16;                    // bit 4
    const int b_kb  = ((lane >> 3) & 1) * 16;              // bit 4
    const int b_sub = ((lane >> 4) & 1) * 8 + (lane & 7);  // pixel-within-pair offset

    // hoisted swizzled A-fragment bases; XOR-combine deltas (bits<7)
    uint32_t aoff[4];
#pragma unroll
    for (int mi = 0; mi < 4; mi++)
        aoff[mi] = swz((uint32_t)((wm * 64 + mi * 16 + a_row) * 128)) ^ (uint32_t)a_kb;

    // fp16 accumulators: 4 mi x 6 ni x 2 regs = 48
    uint32_t ch[4][6][2];
#pragma unroll
    for (int mi = 0; mi < 4; mi++)
#pragma unroll
        for (int ni = 0; ni < 6; ni++) { ch[mi][ni][0] = 0u; ch[mi][ni][1] = 0u; }

    auto stageA = [&](int it) {
        const uint32_t bufA = sb + (uint32_t)(it & 1) * 16384;
        const char* wsrc = (const char*)g_w1 + (size_t)it * 32768 + (size_t)h * 16384;
#pragma unroll
        for (int q = 0; q < 4; q++) {
            int ch2 = tid + q * 256;
            cp16(bufA + ch2 * 16, wsrc + ch2 * 16, true);
        }
        CP_COMMIT();
    };

    // ---- prologue: A0 + slab ----
    stageA(0);
    {
        const int nrows = border ? 241 : 273;   // real rows + zero row
        const int nreal = border ? 240 : 272;
        const int nch = 2 * nrows * 8;
        for (int chix = tid; chix < nch; chix += 256) {
            int plane = chix / (nrows * 8);
            int rem = chix - plane * nrows * 8;
            int r = rem >> 3, j = rem & 7;
            bool valid = false;
            size_t fidx = 0;
            if (r < nreal) {
                if (!border) {
                    int sy = r / 34, sx = r - sy * 34;
                    int gy = ty * 6 - 1 + sy, gx = tx * 32 - 1 + sx;
                    valid = ((unsigned)gy < (unsigned)HF) && ((unsigned)gx < (unsigned)WF);
                    if (valid) fidx = (size_t)(gy * WF + gx);
                } else {
                    int y, x;
                    if (r < 64)        { y = r >> 5; x = r & 31; }
                    else if (r < 128)  { y = 30 + ((r - 64) >> 5); x = r & 31; }
                    else { int q = r - 128; y = 2 + (q >> 2); int cc2 = q & 3;
                           x = (cc2 < 2) ? cc2 : 28 + cc2; }
                    valid = true;
                    fidx = (size_t)((y0 + y) * WF + (x0 + x));
                }
            }
            const char* src = (const char*)g_feat + fidx * 256 + plane * 128 + j * 16;
            cp16(sb + SLAB_OFF + (uint32_t)plane * PLANE_BYTES + swz((uint32_t)(r * 128 + j * 16)),
                 src, valid);
        }
        CP_COMMIT();
    }
    const int zrow = border ? 240 : 272;

    for (int tap = 0; tap < 9; ++tap) {
        const int dy = tap / 3 - 1, dx = tap % 3 - 1;

        // swizzled B-fragment bases for this tap (3 ni-pairs); XOR-combined kb
        uint32_t boff[3];
#pragma unroll
        for (int nb = 0; nb < 3; nb++) {
            int p = wn * 48 + nb * 16 + b_sub;
            int r;
            if (!border) {
                int py = p >> 5, px = p & 31;
                int gy = ty * 6 + py + dy, gx = tx * 32 + px + dx;
                bool v = ((unsigned)gy < (unsigned)HF) && ((unsigned)gx < (unsigned)WF);
                r = v ? ((py + 1 + dy) * 34 + (px + 1 + dx)) : zrow;
            } else {
                int ly, lx;
                bool pin = p < 124;
                ring2yx(pin ? p : 0, ly, lx);
                int ny = ly + dy, nx = lx + dx;
                bool v = pin && ((unsigned)ny < 32u) && ((unsigned)nx < 32u);
                r = v ? frame2row(ny, nx) : zrow;
            }
            boff[nb] = swz((uint32_t)(r * 128)) ^ (uint32_t)b_kb;
        }

#pragma unroll
        for (int cc = 0; cc < 2; ++cc) {
            const int it = tap * 2 + cc;
            CP_WAIT0();
            __syncthreads();
            if (it < 17) stageA(it + 1);   // overlaps with MMA below; buffer freed by barrier

            const uint32_t sA = sb + (uint32_t)(it & 1) * 16384;
            const uint32_t pB = sb + SLAB_OFF + (uint32_t)cc * PLANE_BYTES;

#pragma unroll
            for (int ks = 0; ks < 4; ks++) {
                const uint32_t d = (uint32_t)(ks * 32);
                uint32_t af[4][4], bf[3][4];
#pragma unroll
                for (int mi = 0; mi < 4; mi++)
                    ldsm_x4(af[mi][0], af[mi][1], af[mi][2], af[mi][3],
                            sA + (aoff[mi] ^ d));
#pragma unroll
                for (int nb = 0; nb < 3; nb++)
                    ldsm_x4(bf[nb][0], bf[nb][1], bf[nb][2], bf[nb][3],
                            pB + (boff[nb] ^ d));
#pragma unroll
                for (int mi = 0; mi < 4; mi++)
#pragma unroll
                    for (int ni = 0; ni < 6; ni++) {
                        const int nb = ni >> 1, sel = (ni & 1) * 2;
                        asm volatile(
                            "mma.sync.aligned.m16n8k16.row.col.f16.f16.f16.f16 "
                            "{%0,%1}, {%2,%3,%4,%5}, {%6,%7}, {%0,%1};"
                            : "+r"(ch[mi][ni][0]), "+r"(ch[mi][ni][1])
                            : "r"(af[mi][0]), "r"(af[mi][1]),
                              "r"(af[mi][2]), "r"(af[mi][3]),
                              "r"(bf[nb][sel]), "r"(bf[nb][sel + 1]));
                    }
            }
        }
    }
    __syncthreads();

    // ---- fused conv2 epilogue (partial over this oc half) ----
    float* w2s = (float*)smem;                    // [256][9] fp32
    float* tpart = (float*)(smem + 12288);        // [2 wm][192 px][9] = 13824B
    for (int i = tid; i < 2304; i += 256) w2s[i] = W2[i];
    __syncthreads();

    float bA[4], bB[4];
#pragma unroll
    for (int mi = 0; mi < 4; mi++) {
        bA[mi] = b1[h * 128 + wm * 64 + mi * 16 + g];
        bB[mi] = b1[h * 128 + wm * 64 + mi * 16 + g + 8];
    }

#pragma unroll
    for (int ni = 0; ni < 6; ni++) {
        float pt0[9], pt1[9];
#pragma unroll
        for (int t = 0; t < 9; t++) { pt0[t] = 0.f; pt1[t] = 0.f; }
#pragma unroll
        for (int mi = 0; mi < 4; mi++) {
            const int ocA = h * 128 + wm * 64 + mi * 16 + g;
            float2 lo = __half22float2(*(__half2*)&ch[mi][ni][0]);
            float2 hi = __half22float2(*(__half2*)&ch[mi][ni][1]);
            const float h0 = fmaxf(lo.x + bA[mi], 0.f);
            const float h1 = fmaxf(lo.y + bA[mi], 0.f);
            const float h2 = fmaxf(hi.x + bB[mi], 0.f);
            const float h3 = fmaxf(hi.y + bB[mi], 0.f);
            const float* wA = &w2s[ocA * 9];
            const float* wB = &w2s[(ocA + 8) * 9];
#pragma unroll
            for (int t = 0; t < 9; t++) {
                pt0[t] += h0 * wA[t] + h2 * wB[t];
                pt1[t] += h1 * wA[t] + h3 * wB[t];
            }
        }
#pragma unroll
        for (int m = 4; m <= 16; m <<= 1) {
#pragma unroll
            for (int t = 0; t < 9; t++) {
                pt0[t] += __shfl_xor_sync(0xffffffffu, pt0[t], m);
                pt1[t] += __shfl_xor_sync(0xffffffffu, pt1[t], m);
            }
        }
        if (g == 0) {
            const int pxl = wn * 48 + ni * 8 + tig * 2;
            float* d0 = &tpart[((size_t)wm * 192 + pxl) * 9];
#pragma unroll
            for (int t = 0; t < 9; t++) d0[t] = pt0[t];
#pragma unroll
            for (int t = 0; t < 9; t++) d0[9 + t] = pt1[t];
        }
    }
    __syncthreads();

    for (int i = tid; i < 1728; i += 256) {
        float v = tpart[i] + tpart[1728 + i];
        int p = i / 9, t = i - p * 9;
        if (!border) {
            int py = ty * 6 + (p >> 5);
            int px = tx * 32 + (p & 31);
            if (py < HF)
                g_Tp[h][((size_t)py * WF + px) * 9 + t] = v;
        } else if (p < 124) {
            g_Tbp[h][((size_t)a * 124 + p) * 9 + t] = v;
        }
    }
}

// ---------------- final: sum halves + border override + BCE + per-anchor mean ----------
__global__ __launch_bounds__(256) void k_final(const int* __restrict__ anchors,
                                               const int* __restrict__ labels,
                                               const int* __restrict__ base_classes,
                                               const int* __restrict__ seg,
                                               const float* __restrict__ b2) {
    __shared__ float Ts[1024 * 9];
    __shared__ float red[8];
    const int a = blockIdx.x, tid = threadIdx.x;
    const int x0 = anchors[a * 4 + 0], y0 = anchors[a * 4 + 2];
    for (int i = tid; i < 9216; i += 256) {
        int p = i / 9, t = i - p * 9;
        int ly = p >> 5, lx = p & 31;
        size_t idx = ((size_t)(y0 + ly) * WF + (x0 + lx)) * 9 + t;
        Ts[i] = g_Tp[0][idx] + g_Tp[1][idx];
    }
    __syncthreads();
    if (tid < 124) {
        int ly, lx;
        ring2yx(tid, ly, lx);
        size_t idx = (size_t)a * 124 * 9 + (size_t)tid * 9;
        float* dst = &Ts[(ly * 32 + lx) * 9];
#pragma unroll
        for (int t = 0; t < 9; t++) dst[t] = g_Tbp[0][idx + t] + g_Tbp[1][idx + t];
    }
    const int tc = base_classes[labels[a]];
    const float b2v = b2[0];
    __syncthreads();
    float acc = 0.0f;
    for (int q = tid; q < 1024; q += 256) {
        const int qy = q >> 5, qx = q & 31;
        float l = b2v;
#pragma unroll
        for (int t = 0; t < 9; t++) {
            const int ny = qy + t / 3 - 1, nx = qx + t % 3 - 1;
            if ((unsigned)ny < 32u && (unsigned)nx < 32u) l += Ts[(ny * 32 + nx) * 9 + t];
        }
        const int sv = seg[(size_t)(4 * (y0 + qy)) * 1280 + 4 * (x0 + qx)];
        const float tg = (sv == tc) ? 1.0f : 0.0f;
        acc += fmaxf(l, 0.0f) - l * tg + log1pf(__expf(-fabsf(l)));
    }
#pragma unroll
    for (int o = 16; o; o >>= 1) acc += __shfl_xor_sync(0xffffffffu, acc, o);
    if ((tid & 31) == 0) red[tid >> 5] = acc;
    __syncthreads();
    if (tid < 32) {
        float v = (tid < 8) ? red[tid] : 0.0f;
#pragma unroll
        for (int o = 4; o; o >>= 1) v += __shfl_xor_sync(0xffffffffu, v, o);
        if (tid == 0) g_partial[a] = v * (1.0f / 1024.0f);
    }
}

__global__ __launch_bounds__(256) void k_reduce(float* __restrict__ out) {
    __shared__ float s[256];
    const int tid = threadIdx.x;
    s[tid] = g_partial[tid];
    __syncthreads();
#pragma unroll
    for (int o = 128; o; o >>= 1) {
        if (tid < o) s[tid] += s[tid + o];
        __syncthreads();
    }
    if (tid == 0) out[0] = s[0] / (256.0f + 1e-10f);
}

// ---------------- launch ----------------
extern "C" void kernel_launch(void* const* d_in, const int* in_sizes, int n_in,
                              void* d_out, int out_size) {
    (void)in_sizes; (void)n_in; (void)out_size;
    const float* fm      = (const float*)d_in[0];
    const int*   seg     = (const int*)d_in[1];
    const int*   anchors = (const int*)d_in[2];
    const int*   labels  = (const int*)d_in[3];
    const int*   bclass  = (const int*)d_in[4];
    const float* W1      = (const float*)d_in[5];
    const float* b1      = (const float*)d_in[6];
    const float* W2      = (const float*)d_in[7];
    const float* b2      = (const float*)d_in[8];

    cudaFuncSetAttribute(k_conv, cudaFuncAttributeMaxDynamicSharedMemorySize, 102656);

    k_prep_feat<<<dim3(3200, 4), 256>>>(fm);
    k_prep_w1<<<1152, 256>>>(W1);
    k_zero<<<1, 256>>>();
    k_conv<<<1592, 256, 102656>>>(anchors, b1, W2);
    k_final<<<256, 256>>>(anchors, labels, bclass, seg, b2);
    k_reduce<<<1, 256>>>((float*)d_out);
}

// round 16
// speedup vs baseline: 1.1386x; 1.1386x over previous
#include <cuda_runtime.h>
#include <cuda_fp16.h>
#include <cstdint>
#include <math.h>

#define HF 320
#define WF 320

// ---------------- global scratch ----------------
__device__ __align__(16) __half g_feat[(size_t)HF * WF * 128];   // [y][x][ic] fp16, 26 MB
__device__ __align__(16) __half g_w1[18 * 256 * 64];             // swizzled A tiles fp16
__device__ __align__(16) float g_Tp[2][(size_t)HF * WF * 9];     // partial T (oc halves)
__device__ __align__(16) float g_Tbp[2][(size_t)256 * 124 * 9];  // partial border ring
__device__ float g_partial[256];

// ---------------- helpers ----------------
__device__ __forceinline__ uint32_t smem_u32(const void* p) {
    uint32_t a;
    asm("{ .reg .u64 t; cvta.to.shared.u64 t, %1; cvt.u32.u64 %0, t; }" : "=r"(a) : "l"(p));
    return a;
}
__device__ __forceinline__ uint32_t swz(uint32_t o) { return o ^ ((o >> 3) & 0x70); }

__device__ __forceinline__ void cp16(uint32_t dst, const void* src, bool valid) {
    unsigned long long gsrc;
    asm("cvta.to.global.u64 %0, %1;" : "=l"(gsrc) : "l"(src));
    int sz = valid ? 16 : 0;
    asm volatile("cp.async.ca.shared.global [%0], [%1], 16, %2;" :: "r"(dst), "l"(gsrc), "r"(sz));
}
#define CP_COMMIT() asm volatile("cp.async.commit_group;")
#define CP_WAIT1()  asm volatile("cp.async.wait_group 1;")
#define CP_WAIT0()  asm volatile("cp.async.wait_group 0;")

__device__ __forceinline__ void ldsm_x4(uint32_t& r0, uint32_t& r1, uint32_t& r2, uint32_t& r3,
                                        uint32_t addr) {
    asm volatile("ldmatrix.sync.aligned.m8n8.x4.shared.b16 {%0,%1,%2,%3}, [%4];"
                 : "=r"(r0), "=r"(r1), "=r"(r2), "=r"(r3) : "r"(addr));
}

// ring index <-> local (y,x) on the crop border (124 px)
__device__ __forceinline__ void ring2yx(int idx, int& y, int& x) {
    if (idx < 32)      { y = 0;              x = idx; }
    else if (idx < 64) { y = 31;             x = idx - 32; }
    else if (idx < 94) { y = 1 + (idx - 64); x = 0; }
    else               { y = 1 + (idx - 94); x = 31; }
}
// width-2 frame of the 32x32 crop: 240 rows
__device__ __forceinline__ int frame2row(int y, int x) {
    if (y < 2)   return y * 32 + x;
    if (y >= 30) return 64 + (y - 30) * 32 + x;
    return 128 + (y - 2) * 4 + ((x < 2) ? x : x - 28);
}

// ---------------- P0: feature fp32 [ic][y][x] -> fp16 [y][x][ic] ----------------
__global__ __launch_bounds__(256) void k_prep_feat(const float* __restrict__ f) {
    __shared__ float s[32][33];
    int t = threadIdx.x;
    int bx = blockIdx.x;           // y*10 + xt
    int y = bx / 10, xt = bx % 10;
    int ict = blockIdx.y;          // 4 chunks of 32 ic
    int lx = t & 31, lr = t >> 5;
#pragma unroll
    for (int i = 0; i < 4; i++) {
        int ic = i * 8 + lr;
        s[ic][lx] = f[(size_t)(ict * 32 + ic) * (HF * WF) + (size_t)y * WF + xt * 32 + lx];
    }
    __syncthreads();
#pragma unroll
    for (int i = 0; i < 4; i++) {
        int x = i * 8 + lr;
        g_feat[((size_t)y * WF + xt * 32 + x) * 128 + ict * 32 + lx] = __float2half(s[lx][x]);
    }
}

// ---------------- P1: W1 fp32 [256][128][3][3] -> swizzled fp16 A tiles ----------------
__global__ __launch_bounds__(256) void k_prep_w1(const float* __restrict__ W1) {
    int e = blockIdx.x * 256 + threadIdx.x;   // < 294912
    int i = e & 63;            // ic within chunk
    int r = (e >> 6) & 255;    // oc
    int bi = e >> 14;          // 0..17
    int tap = bi >> 1, c = bi & 1;
    float v = W1[((size_t)r * 128 + c * 64 + i) * 9 + tap];
    *(__half*)((char*)g_w1 + (size_t)bi * 32768 + swz((uint32_t)(r * 128 + i * 2))) =
        __float2half(v);
}

// ---------------- tiny 3rd launch (keeps k_conv as the profiled 4th launch) -------------
__global__ void k_zero() { g_partial[threadIdx.x] = 0.0f; }

// ---------------- conv: M-split pairs. map (bx<1600) + border (bx>=1600) ---------------
// 256 thr = 8 warps (2wm x 4wn), occ 2/SM. Each CTA: M=128 oc (half h), N=128 px,
// K=1152 (tap 0..8 x chunk 0..1 x ks 0..3). B fragments preloaded BEFORE the barrier
// (slab is immutable after prologue), so only A-ldsm + HMMA sit on the post-barrier path.
// SMEM 111616B: A ring buf0/1/2 [0,48K), slab plane0 [49152,+31232), plane1 [+31232).
#define PLANE_BYTES 31232     // 244 rows x 128B
#define SLAB_OFF    49152
__global__ __launch_bounds__(256, 2) void k_conv(const int* __restrict__ anchors,
                                                 const float* __restrict__ b1,
                                                 const float* __restrict__ W2) {
    extern __shared__ char smem[];
    const int tid = threadIdx.x, lane = tid & 31, wid = tid >> 5;
    const int g = lane >> 2, tig = lane & 3;
    const int wm = wid >> 2, wn = wid & 3;         // wm 0..1, wn 0..3
    const int bx = blockIdx.x;
    const bool border = (bx >= 1600);
    int ty = 0, tx = 0, a = 0, x0 = 0, y0 = 0, h;
    if (!border) { int tile = bx >> 1; h = bx & 1; ty = tile / 10; tx = tile % 10; }
    else { int b = bx - 1600; a = b >> 1; h = b & 1;
           x0 = anchors[a * 4 + 0]; y0 = anchors[a * 4 + 2]; }
    const uint32_t sb = smem_u32(smem);

    const int a_row = (lane & 7) + ((lane >> 3) & 1) * 8;
    const int a_kb  = (lane >> 4) * 16;                    // bit 4
    const int b_kb  = ((lane >> 3) & 1) * 16;              // bit 4
    const int b_sub = ((lane >> 4) & 1) * 8 + (lane & 7);  // pixel-within-pair offset

    // hoisted swizzled A-fragment bases; XOR-combine deltas (bits<7)
    uint32_t aoff[4];
#pragma unroll
    for (int mi = 0; mi < 4; mi++)
        aoff[mi] = swz((uint32_t)((wm * 64 + mi * 16 + a_row) * 128)) ^ (uint32_t)a_kb;

    // fp16 accumulators
    uint32_t ch[4][4][2];
#pragma unroll
    for (int mi = 0; mi < 4; mi++)
#pragma unroll
        for (int ni = 0; ni < 4; ni++) { ch[mi][ni][0] = 0u; ch[mi][ni][1] = 0u; }

    auto stageA = [&](int it) {
        const uint32_t bufA = sb + (uint32_t)(it % 3) * 16384;
        const char* wsrc = (const char*)g_w1 + (size_t)it * 32768 + (size_t)h * 16384;
#pragma unroll
        for (int q = 0; q < 4; q++) {
            int ch2 = tid + q * 256;
            cp16(bufA + ch2 * 16, wsrc + ch2 * 16, true);
        }
        CP_COMMIT();
    };

    // ---- prologue: A0, slab, A1 ----
    stageA(0);
    {
        const int nrows = border ? 244 : 212;
        const int nch = 2 * nrows * 8;
        for (int chix = tid; chix < nch; chix += 256) {
            int plane = chix / (nrows * 8);
            int rem = chix - plane * nrows * 8;
            int r = rem >> 3, j = rem & 7;
            bool valid = false;
            size_t fidx = 0;
            if (!border) {
                if (r < 204) {
                    int sy = r / 34, sx = r - sy * 34;
                    int gy = ty * 4 - 1 + sy, gx = tx * 32 - 1 + sx;
                    valid = ((unsigned)gy < (unsigned)HF) && ((unsigned)gx < (unsigned)WF);
                    if (valid) fidx = (size_t)(gy * WF + gx);
                }
            } else {
                if (r < 240) {
                    int y, x;
                    if (r < 64)        { y = r >> 5; x = r & 31; }
                    else if (r < 128)  { y = 30 + ((r - 64) >> 5); x = r & 31; }
                    else { int q = r - 128; y = 2 + (q >> 2); int cc2 = q & 3;
                           x = (cc2 < 2) ? cc2 : 28 + cc2; }
                    valid = true;
                    fidx = (size_t)((y0 + y) * WF + (x0 + x));
                }
            }
            const char* src = (const char*)g_feat + fidx * 256 + plane * 128 + j * 16;
            cp16(sb + SLAB_OFF + (uint32_t)plane * PLANE_BYTES + swz((uint32_t)(r * 128 + j * 16)),
                 src, valid);
        }
        CP_COMMIT();
    }
    stageA(1);
    const int zrow = border ? 240 : 204;

    for (int tap = 0; tap < 9; ++tap) {
        const int dy = tap / 3 - 1, dx = tap % 3 - 1;

        // swizzled B-fragment bases for this tap (both cc planes); XOR-combined kb
        uint32_t boff[2];
#pragma unroll
        for (int nb = 0; nb < 2; nb++) {
            int p = wn * 32 + nb * 16 + b_sub;
            int r;
            if (!border) {
                int py = p >> 5, px = p & 31;
                int gy = ty * 4 + py + dy, gx = tx * 32 + px + dx;
                bool v = ((unsigned)gy < (unsigned)HF) && ((unsigned)gx < (unsigned)WF);
                r = v ? ((py + 1 + dy) * 34 + (px + 1 + dx)) : zrow;
            } else {
                int ly, lx;
                bool pin = p < 124;
                ring2yx(pin ? p : 0, ly, lx);
                int ny = ly + dy, nx = lx + dx;
                bool v = pin && ((unsigned)ny < 32u) && ((unsigned)nx < 32u);
                r = v ? frame2row(ny, nx) : zrow;
            }
            boff[nb] = swz((uint32_t)(r * 128)) ^ (uint32_t)b_kb;
        }

#pragma unroll
        for (int cc = 0; cc < 2; ++cc) {
            const int it = tap * 2 + cc;
            const uint32_t pB = sb + SLAB_OFF + (uint32_t)cc * PLANE_BYTES;

            // ---- preload ALL B fragments for this iteration (slab is immutable;
            //      no dependence on the barrier below — latency hides under it) ----
            uint32_t bf[4][2][4];
#pragma unroll
            for (int ks = 0; ks < 4; ks++) {
                const uint32_t d = (uint32_t)(ks * 32);
#pragma unroll
                for (int nb = 0; nb < 2; nb++)
                    ldsm_x4(bf[ks][nb][0], bf[ks][nb][1], bf[ks][nb][2], bf[ks][nb][3],
                            pB + (boff[nb] ^ d));
            }

            if (it < 17) { CP_WAIT1(); }
            else         { CP_WAIT0(); }
            __syncthreads();
            if (it < 16) stageA(it + 2);

            const uint32_t sA = sb + (uint32_t)(it % 3) * 16384;

#pragma unroll
            for (int ks = 0; ks < 4; ks++) {
                const uint32_t d = (uint32_t)(ks * 32);
                uint32_t af[4][4];
#pragma unroll
                for (int mi = 0; mi < 4; mi++)
                    ldsm_x4(af[mi][0], af[mi][1], af[mi][2], af[mi][3],
                            sA + (aoff[mi] ^ d));
#pragma unroll
                for (int mi = 0; mi < 4; mi++)
#pragma unroll
                    for (int ni = 0; ni < 4; ni++) {
                        const int nb = ni >> 1, sel = (ni & 1) * 2;
                        asm volatile(
                            "mma.sync.aligned.m16n8k16.row.col.f16.f16.f16.f16 "
                            "{%0,%1}, {%2,%3,%4,%5}, {%6,%7}, {%0,%1};"
                            : "+r"(ch[mi][ni][0]), "+r"(ch[mi][ni][1])
                            : "r"(af[mi][0]), "r"(af[mi][1]),
                              "r"(af[mi][2]), "r"(af[mi][3]),
                              "r"(bf[ks][nb][sel]), "r"(bf[ks][nb][sel + 1]));
                    }
            }
        }
    }
    __syncthreads();

    // ---- fused conv2 epilogue (partial over this oc half) ----
    float* w2s = (float*)smem;                    // [256][9] fp32
    float* tpart = (float*)(smem + 12288);        // [2 wm][128 px][9]
    for (int i = tid; i < 2304; i += 256) w2s[i] = W2[i];
    __syncthreads();

    float bA[4], bB[4];
#pragma unroll
    for (int mi = 0; mi < 4; mi++) {
        bA[mi] = b1[h * 128 + wm * 64 + mi * 16 + g];
        bB[mi] = b1[h * 128 + wm * 64 + mi * 16 + g + 8];
    }

#pragma unroll
    for (int ni = 0; ni < 4; ni++) {
        float pt0[9], pt1[9];
#pragma unroll
        for (int t = 0; t < 9; t++) { pt0[t] = 0.f; pt1[t] = 0.f; }
#pragma unroll
        for (int mi = 0; mi < 4; mi++) {
            const int ocA = h * 128 + wm * 64 + mi * 16 + g;
            float2 lo = __half22float2(*(__half2*)&ch[mi][ni][0]);
            float2 hi = __half22float2(*(__half2*)&ch[mi][ni][1]);
            const float h0 = fmaxf(lo.x + bA[mi], 0.f);
            const float h1 = fmaxf(lo.y + bA[mi], 0.f);
            const float h2 = fmaxf(hi.x + bB[mi], 0.f);
            const float h3 = fmaxf(hi.y + bB[mi], 0.f);
            const float* wA = &w2s[ocA * 9];
            const float* wB = &w2s[(ocA + 8) * 9];
#pragma unroll
            for (int t = 0; t < 9; t++) {
                pt0[t] += h0 * wA[t] + h2 * wB[t];
                pt1[t] += h1 * wA[t] + h3 * wB[t];
            }
        }
#pragma unroll
        for (int m = 4; m <= 16; m <<= 1) {
#pragma unroll
            for (int t = 0; t < 9; t++) {
                pt0[t] += __shfl_xor_sync(0xffffffffu, pt0[t], m);
                pt1[t] += __shfl_xor_sync(0xffffffffu, pt1[t], m);
            }
        }
        if (g == 0) {
            const int pxl = wn * 32 + ni * 8 + tig * 2;
            float* d0 = &tpart[((size_t)wm * 128 + pxl) * 9];
#pragma unroll
            for (int t = 0; t < 9; t++) d0[t] = pt0[t];
#pragma unroll
            for (int t = 0; t < 9; t++) d0[9 + t] = pt1[t];
        }
    }
    __syncthreads();

    for (int i = tid; i < 1152; i += 256) {
        float v = tpart[i] + tpart[1152 + i];
        int p = i / 9, t = i - p * 9;
        if (!border) {
            int py = ty * 4 + (p >> 5);
            int px = tx * 32 + (p & 31);
            g_Tp[h][((size_t)py * WF + px) * 9 + t] = v;
        } else if (p < 124) {
            g_Tbp[h][((size_t)a * 124 + p) * 9 + t] = v;
        }
    }
}

// ---------------- final: sum halves + border override + BCE + per-anchor mean ----------
__global__ __launch_bounds__(256) void k_final(const int* __restrict__ anchors,
                                               const int* __restrict__ labels,
                                               const int* __restrict__ base_classes,
                                               const int* __restrict__ seg,
                                               const float* __restrict__ b2) {
    __shared__ float Ts[1024 * 9];
    __shared__ float red[8];
    const int a = blockIdx.x, tid = threadIdx.x;
    const int x0 = anchors[a * 4 + 0], y0 = anchors[a * 4 + 2];
    for (int i = tid; i < 9216; i += 256) {
        int p = i / 9, t = i - p * 9;
        int ly = p >> 5, lx = p & 31;
        size_t idx = ((size_t)(y0 + ly) * WF + (x0 + lx)) * 9 + t;
        Ts[i] = g_Tp[0][idx] + g_Tp[1][idx];
    }
    __syncthreads();
    if (tid < 124) {
        int ly, lx;
        ring2yx(tid, ly, lx);
        size_t idx = (size_t)a * 124 * 9 + (size_t)tid * 9;
        float* dst = &Ts[(ly * 32 + lx) * 9];
#pragma unroll
        for (int t = 0; t < 9; t++) dst[t] = g_Tbp[0][idx + t] + g_Tbp[1][idx + t];
    }
    const int tc = base_classes[labels[a]];
    const float b2v = b2[0];
    __syncthreads();
    float acc = 0.0f;
    for (int q = tid; q < 1024; q += 256) {
        const int qy = q >> 5, qx = q & 31;
        float l = b2v;
#pragma unroll
        for (int t = 0; t < 9; t++) {
            const int ny = qy + t / 3 - 1, nx = qx + t % 3 - 1;
            if ((unsigned)ny < 32u && (unsigned)nx < 32u) l += Ts[(ny * 32 + nx) * 9 + t];
        }
        const int sv = seg[(size_t)(4 * (y0 + qy)) * 1280 + 4 * (x0 + qx)];
        const float tg = (sv == tc) ? 1.0f : 0.0f;
        acc += fmaxf(l, 0.0f) - l * tg + log1pf(__expf(-fabsf(l)));
    }
#pragma unroll
    for (int o = 16; o; o >>= 1) acc += __shfl_xor_sync(0xffffffffu, acc, o);
    if ((tid & 31) == 0) red[tid >> 5] = acc;
    __syncthreads();
    if (tid < 32) {
        float v = (tid < 8) ? red[tid] : 0.0f;
#pragma unroll
        for (int o = 4; o; o >>= 1) v += __shfl_xor_sync(0xffffffffu, v, o);
        if (tid == 0) g_partial[a] = v * (1.0f / 1024.0f);
    }
}

__global__ __launch_bounds__(256) void k_reduce(float* __restrict__ out) {
    __shared__ float s[256];
    const int tid = threadIdx.x;
    s[tid] = g_partial[tid];
    __syncthreads();
#pragma unroll
    for (int o = 128; o; o >>= 1) {
        if (tid < o) s[tid] += s[tid + o];
        __syncthreads();
    }
    if (tid == 0) out[0] = s[0] / (256.0f + 1e-10f);
}

// ---------------- launch ----------------
extern "C" void kernel_launch(void* const* d_in, const int* in_sizes, int n_in,
                              void* d_out, int out_size) {
    (void)in_sizes; (void)n_in; (void)out_size;
    const float* fm      = (const float*)d_in[0];
    const int*   seg     = (const int*)d_in[1];
    const int*   anchors = (const int*)d_in[2];
    const int*   labels  = (const int*)d_in[3];
    const int*   bclass  = (const int*)d_in[4];
    const float* W1      = (const float*)d_in[5];
    const float* b1      = (const float*)d_in[6];
    const float* W2      = (const float*)d_in[7];
    const float* b2      = (const float*)d_in[8];

    cudaFuncSetAttribute(k_conv, cudaFuncAttributeMaxDynamicSharedMemorySize, 111616);

    k_prep_feat<<<dim3(3200, 4), 256>>>(fm);
    k_prep_w1<<<1152, 256>>>(W1);
    k_zero<<<1, 256>>>();
    k_conv<<<2112, 256, 111616>>>(anchors, b1, W2);
    k_final<<<256, 256>>>(anchors, labels, bclass, seg, b2);
    k_reduce<<<1, 256>>>((float*)d_out);
}

// round 17
// speedup vs baseline: 1.3179x; 1.1575x over previous
#include <cuda_runtime.h>
#include <cuda_fp16.h>
#include <cstdint>
#include <math.h>

#define HF 320
#define WF 320

// ---------------- global scratch ----------------
__device__ __align__(16) __half g_feat[(size_t)HF * WF * 128];   // [y][x][ic] fp16, 26 MB
// W1 in mma-fragment order: uint4[h:2][it:18][wm:2][ks:4][mi:4][lane:32]
__device__ __align__(16) uint4 g_w1f[36864];                     // 576 KB, L2-resident
__device__ __align__(16) float g_Tp[2][(size_t)HF * WF * 9];     // partial T (oc halves)
__device__ __align__(16) float g_Tbp[2][(size_t)256 * 124 * 9];  // partial border ring
__device__ float g_partial[256];

// ---------------- helpers ----------------
__device__ __forceinline__ uint32_t smem_u32(const void* p) {
    uint32_t a;
    asm("{ .reg .u64 t; cvta.to.shared.u64 t, %1; cvt.u32.u64 %0, t; }" : "=r"(a) : "l"(p));
    return a;
}
__device__ __forceinline__ uint32_t swz(uint32_t o) { return o ^ ((o >> 3) & 0x70); }

__device__ __forceinline__ void cp16(uint32_t dst, const void* src, bool valid) {
    unsigned long long gsrc;
    asm("cvta.to.global.u64 %0, %1;" : "=l"(gsrc) : "l"(src));
    int sz = valid ? 16 : 0;
    asm volatile("cp.async.ca.shared.global [%0], [%1], 16, %2;" :: "r"(dst), "l"(gsrc), "r"(sz));
}
#define CP_COMMIT() asm volatile("cp.async.commit_group;")
#define CP_WAIT0()  asm volatile("cp.async.wait_group 0;")

__device__ __forceinline__ void ldsm_x4(uint32_t& r0, uint32_t& r1, uint32_t& r2, uint32_t& r3,
                                        uint32_t addr) {
    asm volatile("ldmatrix.sync.aligned.m8n8.x4.shared.b16 {%0,%1,%2,%3}, [%4];"
                 : "=r"(r0), "=r"(r1), "=r"(r2), "=r"(r3) : "r"(addr));
}

// ring index <-> local (y,x) on the crop border (124 px)
__device__ __forceinline__ void ring2yx(int idx, int& y, int& x) {
    if (idx < 32)      { y = 0;              x = idx; }
    else if (idx < 64) { y = 31;             x = idx - 32; }
    else if (idx < 94) { y = 1 + (idx - 64); x = 0; }
    else               { y = 1 + (idx - 94); x = 31; }
}
// width-2 frame of the 32x32 crop: 240 rows
__device__ __forceinline__ int frame2row(int y, int x) {
    if (y < 2)   return y * 32 + x;
    if (y >= 30) return 64 + (y - 30) * 32 + x;
    return 128 + (y - 2) * 4 + ((x < 2) ? x : x - 28);
}

// ---------------- P0: feature fp32 [ic][y][x] -> fp16 [y][x][ic] ----------------
__global__ __launch_bounds__(256) void k_prep_feat(const float* __restrict__ f) {
    __shared__ float s[32][33];
    int t = threadIdx.x;
    int bx = blockIdx.x;           // y*10 + xt
    int y = bx / 10, xt = bx % 10;
    int ict = blockIdx.y;          // 4 chunks of 32 ic
    int lx = t & 31, lr = t >> 5;
#pragma unroll
    for (int i = 0; i < 4; i++) {
        int ic = i * 8 + lr;
        s[ic][lx] = f[(size_t)(ict * 32 + ic) * (HF * WF) + (size_t)y * WF + xt * 32 + lx];
    }
    __syncthreads();
#pragma unroll
    for (int i = 0; i < 4; i++) {
        int x = i * 8 + lr;
        g_feat[((size_t)y * WF + xt * 32 + x) * 128 + ict * 32 + lx] = __float2half(s[lx][x]);
    }
}

// ---------------- P1: W1 fp32 [256][128][3][3] -> fragment-ordered uint32 ---------------
// uint32 e = h*73728 + it*4096 + wm*2048 + ks*512 + mi*128 + lane*4 + reg
__global__ __launch_bounds__(256) void k_prep_w1(const float* __restrict__ W1) {
    int e = blockIdx.x * 256 + threadIdx.x;   // < 147456
    int h = e / 73728, e1 = e % 73728;
    int it = e1 >> 12;
    int e2 = e1 & 4095;
    int wm = e2 >> 11, ks = (e2 >> 9) & 3, mi = (e2 >> 7) & 3,
        lane = (e2 >> 2) & 31, reg = e2 & 3;
    int tap = it >> 1, cc = it & 1;
    int oc = h * 128 + wm * 64 + mi * 16 + (lane >> 2) + (reg & 1) * 8;
    int ic = cc * 64 + ks * 16 + (lane & 3) * 2 + (reg >> 1) * 8;
    unsigned short lo = __half_as_ushort(__float2half(W1[((size_t)oc * 128 + ic) * 9 + tap]));
    unsigned short hi = __half_as_ushort(__float2half(W1[((size_t)oc * 128 + ic + 1) * 9 + tap]));
    ((uint32_t*)g_w1f)[e] = ((uint32_t)hi << 16) | (uint32_t)lo;
}

// ---------------- tiny 3rd launch (keeps k_conv as the profiled 4th launch) -------------
__global__ void k_zero() { g_partial[threadIdx.x] = 0.0f; }

// ---------------- conv: M-split pairs. map (bx<1600) + border (bx>=1600) ---------------
// 256 thr = 8 warps (2wm x 4wn), occ 2/SM. Each CTA: M=128 oc (half h), N=128 px,
// K=1152 (tap 0..8 x chunk 0..1 x ks 0..3). NO mainloop barriers: B slab staged once
// (immutable), A read via coalesced LDG.128 from fragment-ordered g_w1f (L1/L2-resident).
// SMEM 62464B: slab plane0 [0,31232), plane1 [31232,62464). Epilogue reuses [0,26112).
#define PLANE_BYTES 31232     // 244 rows x 128B
__global__ __launch_bounds__(256, 2) void k_conv(const int* __restrict__ anchors,
                                                 const float* __restrict__ b1,
                                                 const float* __restrict__ W2) {
    extern __shared__ char smem[];
    const int tid = threadIdx.x, lane = tid & 31, wid = tid >> 5;
    const int g = lane >> 2, tig = lane & 3;
    const int wm = wid >> 2, wn = wid & 3;         // wm 0..1, wn 0..3
    const int bx = blockIdx.x;
    const bool border = (bx >= 1600);
    int ty = 0, tx = 0, a = 0, x0 = 0, y0 = 0, h;
    if (!border) { int tile = bx >> 1; h = bx & 1; ty = tile / 10; tx = tile % 10; }
    else { int b = bx - 1600; a = b >> 1; h = b & 1;
           x0 = anchors[a * 4 + 0]; y0 = anchors[a * 4 + 2]; }
    const uint32_t sb = smem_u32(smem);

    const int b_kb  = ((lane >> 3) & 1) * 16;              // bit 4
    const int b_sub = ((lane >> 4) & 1) * 8 + (lane & 7);  // pixel-within-pair offset

    // fp16 accumulators
    uint32_t ch[4][4][2];
#pragma unroll
    for (int mi = 0; mi < 4; mi++)
#pragma unroll
        for (int ni = 0; ni < 4; ni++) { ch[mi][ni][0] = 0u; ch[mi][ni][1] = 0u; }

    // ---- prologue: stage B slab once ----
    {
        const int nrows = border ? 244 : 212;
        const int nch = 2 * nrows * 8;
        for (int chix = tid; chix < nch; chix += 256) {
            int plane = chix / (nrows * 8);
            int rem = chix - plane * nrows * 8;
            int r = rem >> 3, j = rem & 7;
            bool valid = false;
            size_t fidx = 0;
            if (!border) {
                if (r < 204) {
                    int sy = r / 34, sx = r - sy * 34;
                    int gy = ty * 4 - 1 + sy, gx = tx * 32 - 1 + sx;
                    valid = ((unsigned)gy < (unsigned)HF) && ((unsigned)gx < (unsigned)WF);
                    if (valid) fidx = (size_t)(gy * WF + gx);
                }
            } else {
                if (r < 240) {
                    int y, x;
                    if (r < 64)        { y = r >> 5; x = r & 31; }
                    else if (r < 128)  { y = 30 + ((r - 64) >> 5); x = r & 31; }
                    else { int q = r - 128; y = 2 + (q >> 2); int cc2 = q & 3;
                           x = (cc2 < 2) ? cc2 : 28 + cc2; }
                    valid = true;
                    fidx = (size_t)((y0 + y) * WF + (x0 + x));
                }
            }
            const char* src = (const char*)g_feat + fidx * 256 + plane * 128 + j * 16;
            cp16(sb + (uint32_t)plane * PLANE_BYTES + swz((uint32_t)(r * 128 + j * 16)),
                 src, valid);
        }
        CP_COMMIT();
        CP_WAIT0();
    }
    __syncthreads();   // slab visible to all warps; NO further barriers until epilogue
    const int zrow = border ? 240 : 204;

    for (int tap = 0; tap < 9; ++tap) {
        const int dy = tap / 3 - 1, dx = tap % 3 - 1;

        // swizzled B-fragment bases for this tap (both cc planes); XOR-combined kb
        uint32_t boff[2];
#pragma unroll
        for (int nb = 0; nb < 2; nb++) {
            int p = wn * 32 + nb * 16 + b_sub;
            int r;
            if (!border) {
                int py = p >> 5, px = p & 31;
                int gy = ty * 4 + py + dy, gx = tx * 32 + px + dx;
                bool v = ((unsigned)gy < (unsigned)HF) && ((unsigned)gx < (unsigned)WF);
                r = v ? ((py + 1 + dy) * 34 + (px + 1 + dx)) : zrow;
            } else {
                int ly, lx;
                bool pin = p < 124;
                ring2yx(pin ? p : 0, ly, lx);
                int ny = ly + dy, nx = lx + dx;
                bool v = pin && ((unsigned)ny < 32u) && ((unsigned)nx < 32u);
                r = v ? frame2row(ny, nx) : zrow;
            }
            boff[nb] = swz((uint32_t)(r * 128)) ^ (uint32_t)b_kb;
        }

#pragma unroll
        for (int cc = 0; cc < 2; ++cc) {
            const int it = tap * 2 + cc;
            const uint32_t pB = sb + (uint32_t)cc * PLANE_BYTES;

            // preload all B fragments for this iteration
            uint32_t bf[4][2][4];
#pragma unroll
            for (int ks = 0; ks < 4; ks++) {
                const uint32_t d = (uint32_t)(ks * 32);
#pragma unroll
                for (int nb = 0; nb < 2; nb++)
                    ldsm_x4(bf[ks][nb][0], bf[ks][nb][1], bf[ks][nb][2], bf[ks][nb][3],
                            pB + (boff[nb] ^ d));
            }

            // A via coalesced LDG.128 from fragment-ordered global, 1-ks lookahead
            const uint4* ap = g_w1f + ((size_t)(h * 18 + it) * 1024 + wm * 512 + lane);
            uint4 a4[2][4];
#pragma unroll
            for (int mi = 0; mi < 4; mi++) a4[0][mi] = ap[mi * 32];

#pragma unroll
            for (int ks = 0; ks < 4; ks++) {
                const int cur = ks & 1, nxt = cur ^ 1;
                if (ks < 3) {
#pragma unroll
                    for (int mi = 0; mi < 4; mi++)
                        a4[nxt][mi] = ap[(ks + 1) * 128 + mi * 32];
                }
#pragma unroll
                for (int mi = 0; mi < 4; mi++) {
                    const uint32_t* af = (const uint32_t*)&a4[cur][mi];
#pragma unroll
                    for (int ni = 0; ni < 4; ni++) {
                        const int nb = ni >> 1, sel = (ni & 1) * 2;
                        asm volatile(
                            "mma.sync.aligned.m16n8k16.row.col.f16.f16.f16.f16 "
                            "{%0,%1}, {%2,%3,%4,%5}, {%6,%7}, {%0,%1};"
                            : "+r"(ch[mi][ni][0]), "+r"(ch[mi][ni][1])
                            : "r"(af[0]), "r"(af[1]), "r"(af[2]), "r"(af[3]),
                              "r"(bf[ks][nb][sel]), "r"(bf[ks][nb][sel + 1]));
                    }
                }
            }
        }
    }
    __syncthreads();

    // ---- fused conv2 epilogue (partial over this oc half) ----
    float* w2s = (float*)smem;                    // [256][9] fp32
    float* tpart = (float*)(smem + 12288);        // [2 wm][128 px][9]
    for (int i = tid; i < 2304; i += 256) w2s[i] = W2[i];
    __syncthreads();

    float bA[4], bB[4];
#pragma unroll
    for (int mi = 0; mi < 4; mi++) {
        bA[mi] = b1[h * 128 + wm * 64 + mi * 16 + g];
        bB[mi] = b1[h * 128 + wm * 64 + mi * 16 + g + 8];
    }

#pragma unroll
    for (int ni = 0; ni < 4; ni++) {
        float pt0[9], pt1[9];
#pragma unroll
        for (int t = 0; t < 9; t++) { pt0[t] = 0.f; pt1[t] = 0.f; }
#pragma unroll
        for (int mi = 0; mi < 4; mi++) {
            const int ocA = h * 128 + wm * 64 + mi * 16 + g;
            float2 lo = __half22float2(*(__half2*)&ch[mi][ni][0]);
            float2 hi = __half22float2(*(__half2*)&ch[mi][ni][1]);
            const float h0 = fmaxf(lo.x + bA[mi], 0.f);
            const float h1 = fmaxf(lo.y + bA[mi], 0.f);
            const float h2 = fmaxf(hi.x + bB[mi], 0.f);
            const float h3 = fmaxf(hi.y + bB[mi], 0.f);
            const float* wA = &w2s[ocA * 9];
            const float* wB = &w2s[(ocA + 8) * 9];
#pragma unroll
            for (int t = 0; t < 9; t++) {
                pt0[t] += h0 * wA[t] + h2 * wB[t];
                pt1[t] += h1 * wA[t] + h3 * wB[t];
            }
        }
#pragma unroll
        for (int m = 4; m <= 16; m <<= 1) {
#pragma unroll
            for (int t = 0; t < 9; t++) {
                pt0[t] += __shfl_xor_sync(0xffffffffu, pt0[t], m);
                pt1[t] += __shfl_xor_sync(0xffffffffu, pt1[t], m);
            }
        }
        if (g == 0) {
            const int pxl = wn * 32 + ni * 8 + tig * 2;
            float* d0 = &tpart[((size_t)wm * 128 + pxl) * 9];
#pragma unroll
            for (int t = 0; t < 9; t++) d0[t] = pt0[t];
#pragma unroll
            for (int t = 0; t < 9; t++) d0[9 + t] = pt1[t];
        }
    }
    __syncthreads();

    for (int i = tid; i < 1152; i += 256) {
        float v = tpart[i] + tpart[1152 + i];
        int p = i / 9, t = i - p * 9;
        if (!border) {
            int py = ty * 4 + (p >> 5);
            int px = tx * 32 + (p & 31);
            g_Tp[h][((size_t)py * WF + px) * 9 + t] = v;
        } else if (p < 124) {
            g_Tbp[h][((size_t)a * 124 + p) * 9 + t] = v;
        }
    }
}

// ---------------- final: sum halves + border override + BCE + per-anchor mean ----------
__global__ __launch_bounds__(256) void k_final(const int* __restrict__ anchors,
                                               const int* __restrict__ labels,
                                               const int* __restrict__ base_classes,
                                               const int* __restrict__ seg,
                                               const float* __restrict__ b2) {
    __shared__ float Ts[1024 * 9];
    __shared__ float red[8];
    const int a = blockIdx.x, tid = threadIdx.x;
    const int x0 = anchors[a * 4 + 0], y0 = anchors[a * 4 + 2];
    for (int i = tid; i < 9216; i += 256) {
        int p = i / 9, t = i - p * 9;
        int ly = p >> 5, lx = p & 31;
        size_t idx = ((size_t)(y0 + ly) * WF + (x0 + lx)) * 9 + t;
        Ts[i] = g_Tp[0][idx] + g_Tp[1][idx];
    }
    __syncthreads();
    if (tid < 124) {
        int ly, lx;
        ring2yx(tid, ly, lx);
        size_t idx = (size_t)a * 124 * 9 + (size_t)tid * 9;
        float* dst = &Ts[(ly * 32 + lx) * 9];
#pragma unroll
        for (int t = 0; t < 9; t++) dst[t] = g_Tbp[0][idx + t] + g_Tbp[1][idx + t];
    }
    const int tc = base_classes[labels[a]];
    const float b2v = b2[0];
    __syncthreads();
    float acc = 0.0f;
    for (int q = tid; q < 1024; q += 256) {
        const int qy = q >> 5, qx = q & 31;
        float l = b2v;
#pragma unroll
        for (int t = 0; t < 9; t++) {
            const int ny = qy + t / 3 - 1, nx = qx + t % 3 - 1;
            if ((unsigned)ny < 32u && (unsigned)nx < 32u) l += Ts[(ny * 32 + nx) * 9 + t];
        }
        const int sv = seg[(size_t)(4 * (y0 + qy)) * 1280 + 4 * (x0 + qx)];
        const float tg = (sv == tc) ? 1.0f : 0.0f;
        acc += fmaxf(l, 0.0f) - l * tg + log1pf(__expf(-fabsf(l)));
    }
#pragma unroll
    for (int o = 16; o; o >>= 1) acc += __shfl_xor_sync(0xffffffffu, acc, o);
    if ((tid & 31) == 0) red[tid >> 5] = acc;
    __syncthreads();
    if (tid < 32) {
        float v = (tid < 8) ? red[tid] : 0.0f;
#pragma unroll
        for (int o = 4; o; o >>= 1) v += __shfl_xor_sync(0xffffffffu, v, o);
        if (tid == 0) g_partial[a] = v * (1.0f / 1024.0f);
    }
}

__global__ __launch_bounds__(256) void k_reduce(float* __restrict__ out) {
    __shared__ float s[256];
    const int tid = threadIdx.x;
    s[tid] = g_partial[tid];
    __syncthreads();
#pragma unroll
    for (int o = 128; o; o >>= 1) {
        if (tid < o) s[tid] += s[tid + o];
        __syncthreads();
    }
    if (tid == 0) out[0] = s[0] / (256.0f + 1e-10f);
}

// ---------------- launch ----------------
extern "C" void kernel_launch(void* const* d_in, const int* in_sizes, int n_in,
                              void* d_out, int out_size) {
    (void)in_sizes; (void)n_in; (void)out_size;
    const float* fm      = (const float*)d_in[0];
    const int*   seg     = (const int*)d_in[1];
    const int*   anchors = (const int*)d_in[2];
    const int*   labels  = (const int*)d_in[3];
    const int*   bclass  = (const int*)d_in[4];
    const float* W1      = (const float*)d_in[5];
    const float* b1      = (const float*)d_in[6];
    const float* W2      = (const float*)d_in[7];
    const float* b2      = (const float*)d_in[8];

    cudaFuncSetAttribute(k_conv, cudaFuncAttributeMaxDynamicSharedMemorySize, 62464);

    k_prep_feat<<<dim3(3200, 4), 256>>>(fm);
    k_prep_w1<<<576, 256>>>(W1);
    k_zero<<<1, 256>>>();
    k_conv<<<2112, 256, 62464>>>(anchors, b1, W2);
    k_final<<<256, 256>>>(anchors, labels, bclass, seg, b2);
    k_reduce<<<1, 256>>>((float*)d_out);
}